// round 11
// baseline (speedup 1.0000x reference)
#include <cuda_runtime.h>
#include <cuda_fp16.h>
#include <cstddef>

#define NUM_USERS 200000
#define NUM_ITEMS 100000
#define N_NODES   (NUM_USERS + NUM_ITEMS)
#define DIM       64
#define NNZ       4000000

#define SCAN_TPB  1024
#define NB_SCAN   ((N_NODES + SCAN_TPB - 1) / SCAN_TPB)   // 293

// Scratch (allocation in kernel_launch is forbidden).
__device__ __half g_h0[(size_t)N_NODES * DIM];
__device__ __half g_h1[(size_t)N_NODES * DIM];
__device__ __half g_h2[(size_t)N_NODES * DIM];
__device__ __half g_h3[(size_t)N_NODES * DIM];
__device__ __align__(16) int2 g_edges[NNZ];   // (col, val-bits), row-sorted
__device__ int    g_cnt[N_NODES];
__device__ int    g_base[N_NODES];
__device__ int    g_row_ptr[N_NODES + 1];
__device__ int    g_blk_sums[NB_SCAN];
__device__ int    g_blk_off[NB_SCAN];

// ---------------------------------------------------------------------------
// init: h0 = fp16(concat(user_emb, item_emb))
// ---------------------------------------------------------------------------
__global__ void init_half_kernel(const float* __restrict__ ue,
                                 const float* __restrict__ ie,
                                 __half* __restrict__ h0) {
    size_t i = (size_t)blockIdx.x * blockDim.x + threadIdx.x;   // float4 index
    const size_t total = (size_t)N_NODES * DIM / 4;
    if (i >= total) return;
    const size_t uf4 = (size_t)NUM_USERS * DIM / 4;
    float4 v;
    if (i < uf4) v = ((const float4*)ue)[i];
    else         v = ((const float4*)ie)[i - uf4];
    __half2 lo = __float22half2_rn(make_float2(v.x, v.y));
    __half2 hi = __float22half2_rn(make_float2(v.z, v.w));
    ((__half2*)h0)[i * 2]     = lo;
    ((__half2*)h0)[i * 2 + 1] = hi;
}

// ---------------------------------------------------------------------------
// CSR build: counting sort of edges by row
// ---------------------------------------------------------------------------
__global__ void zero_cnt_kernel(int* __restrict__ cnt) {
    int i = blockIdx.x * blockDim.x + threadIdx.x;
    if (i < N_NODES) cnt[i] = 0;
}

__global__ void hist_kernel(const int* __restrict__ rows,
                            int* __restrict__ cnt) {
    int e = blockIdx.x * blockDim.x + threadIdx.x;
    if (e < NNZ) atomicAdd(&cnt[rows[e]], 1);
}

__global__ void scan1_kernel(const int* __restrict__ cnt,
                             int* __restrict__ base,
                             int* __restrict__ blk_sums) {
    __shared__ int s[SCAN_TPB];
    int i = blockIdx.x * SCAN_TPB + threadIdx.x;
    int v = (i < N_NODES) ? cnt[i] : 0;
    s[threadIdx.x] = v;
    __syncthreads();
    for (int off = 1; off < SCAN_TPB; off <<= 1) {
        int t = (threadIdx.x >= off) ? s[threadIdx.x - off] : 0;
        __syncthreads();
        s[threadIdx.x] += t;
        __syncthreads();
    }
    if (i < N_NODES) base[i] = s[threadIdx.x] - v;   // exclusive
    if (threadIdx.x == SCAN_TPB - 1) blk_sums[blockIdx.x] = s[SCAN_TPB - 1];
}

__global__ void scan2_kernel(const int* __restrict__ blk_sums,
                             int* __restrict__ blk_off) {
    __shared__ int s[512];
    int i = threadIdx.x;
    int v = (i < NB_SCAN) ? blk_sums[i] : 0;
    s[i] = v;
    __syncthreads();
    for (int off = 1; off < 512; off <<= 1) {
        int t = (i >= off) ? s[i - off] : 0;
        __syncthreads();
        s[i] += t;
        __syncthreads();
    }
    if (i < NB_SCAN) blk_off[i] = s[i] - v;          // exclusive
}

__global__ void rowptr_kernel(const int* __restrict__ base,
                              const int* __restrict__ blk_off,
                              int* __restrict__ row_ptr) {
    int i = blockIdx.x * blockDim.x + threadIdx.x;
    if (i < N_NODES) row_ptr[i] = base[i] + blk_off[i >> 10];
    if (i == 0)      row_ptr[N_NODES] = NNZ;
}

// Permute edges into row-sorted order. Uses cnt (still holding degrees after
// scan) as a countdown cursor: position = row_ptr[r] + (--cnt[r]).
// Within-row order is irrelevant for a sum.
__global__ void scatter_sort_kernel(const float* __restrict__ vals,
                                    const int*   __restrict__ rows,
                                    const int*   __restrict__ cols,
                                    const int*   __restrict__ row_ptr,
                                    int*         __restrict__ cnt,
                                    int2*        __restrict__ edges) {
    int e = blockIdx.x * blockDim.x + threadIdx.x;
    if (e >= NNZ) return;
    int r = rows[e];
    int p = row_ptr[r] + atomicAdd(&cnt[r], -1) - 1;
    edges[p] = make_int2(cols[e], __float_as_int(vals[e]));
}

// ---------------------------------------------------------------------------
// spmm: one warp per row; 8 lanes per edge -> FOUR edges per warp gather LDG.
// Edge metadata for the whole row is preloaded with ONE coalesced warp LDG
// (lane l holds edges[s+l]) and distributed via shfl -> all gathers in a
// chunk are independent (MLP ~= ceil(deg/4)).
// Lane layout: grp = lane>>3 (edge within 4-pack), sub = lane&7 (16 B chunk
// of the 128 B fp16 row). Accumulate 8 fp32/lane; merge via shfl_xor(8,16).
// ---------------------------------------------------------------------------
__global__ void __launch_bounds__(256)
spmm_h_kernel(const int*    __restrict__ row_ptr,
              const int2*   __restrict__ edges,
              const __half* __restrict__ x,
              __half*       __restrict__ y) {
    int w    = (int)(((size_t)blockIdx.x * blockDim.x + threadIdx.x) >> 5);
    int lane = threadIdx.x & 31;
    if (w >= N_NODES) return;

    int s = __ldg(row_ptr + w);
    int e = __ldg(row_ptr + w + 1);

    int grp = lane >> 3;
    int sub = lane & 7;
    float acc[8];
#pragma unroll
    for (int k = 0; k < 8; ++k) acc[k] = 0.f;

    for (int base = s; base < e; base += 32) {
        int idx = base + lane;
        int2 em = make_int2(0, 0);
        if (idx < e) em = __ldg(edges + idx);
        int nsteps = min(e - base, 32);
#pragma unroll 2
        for (int g = 0; g * 4 < nsteps; ++g) {
            int eidx = g * 4 + grp;
            int c  = __shfl_sync(0xffffffffu, em.x, eidx);
            int vb = __shfl_sync(0xffffffffu, em.y, eidx);
            float v = __int_as_float(vb);   // invalid lanes carry v = 0
            uint4 d = __ldg((const uint4*)(x + (size_t)c * DIM) + sub);
            float2 f0 = __half22float2(*(const __half2*)&d.x);
            float2 f1 = __half22float2(*(const __half2*)&d.y);
            float2 f2 = __half22float2(*(const __half2*)&d.z);
            float2 f3 = __half22float2(*(const __half2*)&d.w);
            acc[0] += v * f0.x;  acc[1] += v * f0.y;
            acc[2] += v * f1.x;  acc[3] += v * f1.y;
            acc[4] += v * f2.x;  acc[5] += v * f2.y;
            acc[6] += v * f3.x;  acc[7] += v * f3.y;
        }
    }

    // merge the four edge-groups: lane l += lanes l^8, l^16
#pragma unroll
    for (int k = 0; k < 8; ++k) {
        acc[k] += __shfl_xor_sync(0xffffffffu, acc[k], 8);
        acc[k] += __shfl_xor_sync(0xffffffffu, acc[k], 16);
    }

    if (grp == 0) {   // lanes 0..7 write the 8 x 16 B chunks (128 B row)
        __half2 p0 = __float22half2_rn(make_float2(acc[0], acc[1]));
        __half2 p1 = __float22half2_rn(make_float2(acc[2], acc[3]));
        __half2 p2 = __float22half2_rn(make_float2(acc[4], acc[5]));
        __half2 p3 = __float22half2_rn(make_float2(acc[6], acc[7]));
        uint4 d;
        d.x = *(const unsigned int*)&p0;
        d.y = *(const unsigned int*)&p1;
        d.z = *(const unsigned int*)&p2;
        d.w = *(const unsigned int*)&p3;
        ((uint4*)(y + (size_t)w * DIM))[sub] = d;
    }
}

// ---------------------------------------------------------------------------
// final: out = 0.25 * (emb0_fp32 + h1 + h2 + h3)
// ---------------------------------------------------------------------------
__global__ void final_kernel(const float*  __restrict__ ue,
                             const float*  __restrict__ ie,
                             const __half* __restrict__ h1,
                             const __half* __restrict__ h2,
                             const __half* __restrict__ h3,
                             float* __restrict__ out) {
    size_t i = (size_t)blockIdx.x * blockDim.x + threadIdx.x;   // float4 index
    const size_t total = (size_t)N_NODES * DIM / 4;
    if (i >= total) return;
    const size_t uf4 = (size_t)NUM_USERS * DIM / 4;
    float4 v;
    if (i < uf4) v = ((const float4*)ue)[i];
    else         v = ((const float4*)ie)[i - uf4];

    float2 a0 = __half22float2(((const __half2*)h1)[i * 2]);
    float2 a1 = __half22float2(((const __half2*)h1)[i * 2 + 1]);
    float2 b0 = __half22float2(((const __half2*)h2)[i * 2]);
    float2 b1 = __half22float2(((const __half2*)h2)[i * 2 + 1]);
    float2 c0 = __half22float2(((const __half2*)h3)[i * 2]);
    float2 c1 = __half22float2(((const __half2*)h3)[i * 2 + 1]);

    float4 o;
    o.x = 0.25f * (v.x + a0.x + b0.x + c0.x);
    o.y = 0.25f * (v.y + a0.y + b0.y + c0.y);
    o.z = 0.25f * (v.z + a1.x + b1.x + c1.x);
    o.w = 0.25f * (v.w + a1.y + b1.y + c1.y);
    ((float4*)out)[i] = o;
}

// ---------------------------------------------------------------------------
// launch
// ---------------------------------------------------------------------------
extern "C" void kernel_launch(void* const* d_in, const int* in_sizes, int n_in,
                              void* d_out, int out_size) {
    const float* ue   = (const float*)d_in[0];
    const float* ie   = (const float*)d_in[1];
    const float* vals = (const float*)d_in[2];
    const int*   rows = (const int*)d_in[3];
    const int*   cols = (const int*)d_in[4];
    float* out = (float*)d_out;

    __half *h0, *h1, *h2, *h3;
    int2* edges;
    int *cnt, *base, *row_ptr, *blk_sums, *blk_off;
    cudaGetSymbolAddress((void**)&h0, g_h0);
    cudaGetSymbolAddress((void**)&h1, g_h1);
    cudaGetSymbolAddress((void**)&h2, g_h2);
    cudaGetSymbolAddress((void**)&h3, g_h3);
    cudaGetSymbolAddress((void**)&edges, g_edges);
    cudaGetSymbolAddress((void**)&cnt, g_cnt);
    cudaGetSymbolAddress((void**)&base, g_base);
    cudaGetSymbolAddress((void**)&row_ptr, g_row_ptr);
    cudaGetSymbolAddress((void**)&blk_sums, g_blk_sums);
    cudaGetSymbolAddress((void**)&blk_off, g_blk_off);

    const int TPB = 256;
    const size_t nf4 = (size_t)N_NODES * DIM / 4;           // 4.8M float4s
    const int grid_f4   = (int)((nf4 + TPB - 1) / TPB);
    const int grid_node = (N_NODES + TPB - 1) / TPB;
    const int grid_edge = (NNZ + TPB - 1) / TPB;
    const size_t spmm_threads = (size_t)N_NODES * 32;       // warp per row
    const int grid_spmm = (int)((spmm_threads + TPB - 1) / TPB);

    // ---- build row-sorted CSR (amortized over 3 layers) ----
    zero_cnt_kernel<<<grid_node, TPB>>>(cnt);
    hist_kernel<<<grid_edge, TPB>>>(rows, cnt);
    scan1_kernel<<<NB_SCAN, SCAN_TPB>>>(cnt, base, blk_sums);
    scan2_kernel<<<1, 512>>>(blk_sums, blk_off);
    rowptr_kernel<<<grid_node, TPB>>>(base, blk_off, row_ptr);
    scatter_sort_kernel<<<grid_edge, TPB>>>(vals, rows, cols, row_ptr,
                                            cnt, edges);

    // ---- h0 = fp16(concat embeddings) ----
    init_half_kernel<<<grid_f4, TPB>>>(ue, ie, h0);

    // ---- 3 layers of fp16 SpMM ----
    spmm_h_kernel<<<grid_spmm, TPB>>>(row_ptr, edges, h0, h1);
    spmm_h_kernel<<<grid_spmm, TPB>>>(row_ptr, edges, h1, h2);
    spmm_h_kernel<<<grid_spmm, TPB>>>(row_ptr, edges, h2, h3);

    // ---- out = 0.25 * (emb0 + h1 + h2 + h3) ----
    final_kernel<<<grid_f4, TPB>>>(ue, ie, h1, h2, h3, out);
}

// round 14
// speedup vs baseline: 1.2167x; 1.2167x over previous
#include <cuda_runtime.h>
#include <cuda_fp16.h>
#include <cstddef>

#define NUM_USERS 200000
#define NUM_ITEMS 100000
#define N_NODES   (NUM_USERS + NUM_ITEMS)
#define DIM       64
#define NNZ       4000000

#define SCAN_TPB  1024
#define NB_SCAN   ((N_NODES + SCAN_TPB - 1) / SCAN_TPB)   // 293

// Scratch (allocation in kernel_launch is forbidden).
__device__ __half g_h0[(size_t)N_NODES * DIM];
__device__ __half g_h1[(size_t)N_NODES * DIM];
__device__ __half g_h2[(size_t)N_NODES * DIM];
__device__ __half g_h3[(size_t)N_NODES * DIM];
__device__ __align__(16) int2 g_edges[NNZ];   // (col, val-bits), row-sorted
__device__ int    g_cnt[N_NODES];
__device__ int    g_base[N_NODES];
__device__ int    g_row_ptr[N_NODES + 1];
__device__ int    g_blk_sums[NB_SCAN];
__device__ int    g_blk_off[NB_SCAN];

// ---------------------------------------------------------------------------
// init: h0 = fp16(concat(user_emb, item_emb))
// ---------------------------------------------------------------------------
__global__ void init_half_kernel(const float* __restrict__ ue,
                                 const float* __restrict__ ie,
                                 __half* __restrict__ h0) {
    size_t i = (size_t)blockIdx.x * blockDim.x + threadIdx.x;   // float4 index
    const size_t total = (size_t)N_NODES * DIM / 4;
    if (i >= total) return;
    const size_t uf4 = (size_t)NUM_USERS * DIM / 4;
    float4 v;
    if (i < uf4) v = ((const float4*)ue)[i];
    else         v = ((const float4*)ie)[i - uf4];
    __half2 lo = __float22half2_rn(make_float2(v.x, v.y));
    __half2 hi = __float22half2_rn(make_float2(v.z, v.w));
    ((__half2*)h0)[i * 2]     = lo;
    ((__half2*)h0)[i * 2 + 1] = hi;
}

// ---------------------------------------------------------------------------
// CSR build: counting sort of edges by row
// ---------------------------------------------------------------------------
__global__ void zero_cnt_kernel(int* __restrict__ cnt) {
    int i = blockIdx.x * blockDim.x + threadIdx.x;
    if (i < N_NODES) cnt[i] = 0;
}

__global__ void hist_kernel(const int* __restrict__ rows,
                            int* __restrict__ cnt) {
    int e = blockIdx.x * blockDim.x + threadIdx.x;
    if (e < NNZ) atomicAdd(&cnt[rows[e]], 1);
}

__global__ void scan1_kernel(const int* __restrict__ cnt,
                             int* __restrict__ base,
                             int* __restrict__ blk_sums) {
    __shared__ int s[SCAN_TPB];
    int i = blockIdx.x * SCAN_TPB + threadIdx.x;
    int v = (i < N_NODES) ? cnt[i] : 0;
    s[threadIdx.x] = v;
    __syncthreads();
    for (int off = 1; off < SCAN_TPB; off <<= 1) {
        int t = (threadIdx.x >= off) ? s[threadIdx.x - off] : 0;
        __syncthreads();
        s[threadIdx.x] += t;
        __syncthreads();
    }
    if (i < N_NODES) base[i] = s[threadIdx.x] - v;   // exclusive
    if (threadIdx.x == SCAN_TPB - 1) blk_sums[blockIdx.x] = s[SCAN_TPB - 1];
}

__global__ void scan2_kernel(const int* __restrict__ blk_sums,
                             int* __restrict__ blk_off) {
    __shared__ int s[512];
    int i = threadIdx.x;
    int v = (i < NB_SCAN) ? blk_sums[i] : 0;
    s[i] = v;
    __syncthreads();
    for (int off = 1; off < 512; off <<= 1) {
        int t = (i >= off) ? s[i - off] : 0;
        __syncthreads();
        s[i] += t;
        __syncthreads();
    }
    if (i < NB_SCAN) blk_off[i] = s[i] - v;          // exclusive
}

__global__ void rowptr_kernel(const int* __restrict__ base,
                              const int* __restrict__ blk_off,
                              int* __restrict__ row_ptr) {
    int i = blockIdx.x * blockDim.x + threadIdx.x;
    if (i < N_NODES) row_ptr[i] = base[i] + blk_off[i >> 10];
    if (i == 0)      row_ptr[N_NODES] = NNZ;
}

// Permute edges into row-sorted order. cnt (degrees) is consumed as a
// countdown cursor: position = row_ptr[r] + (--cnt[r]).
__global__ void scatter_sort_kernel(const float* __restrict__ vals,
                                    const int*   __restrict__ rows,
                                    const int*   __restrict__ cols,
                                    const int*   __restrict__ row_ptr,
                                    int*         __restrict__ cnt,
                                    int2*        __restrict__ edges) {
    int e = blockIdx.x * blockDim.x + threadIdx.x;
    if (e >= NNZ) return;
    int r = rows[e];
    int p = row_ptr[r] + atomicAdd(&cnt[r], -1) - 1;
    edges[p] = make_int2(cols[e], __float_as_int(vals[e]));
}

// ---------------------------------------------------------------------------
// spmm: one warp per row; 16 lanes per edge -> TWO edges per warp gather LDG.
// (round-10 structure, unrolled to 8 edges/iteration: 4 int4 edge loads
// issued first, then 4 independent paired gathers -> MLP ~4.)
// Lane layout: half = lane>>4 picks the edge of a pair, sub = lane&15 picks
// the 8 B chunk of the 128 B fp16 row. fp32 accum; shfl_xor(16) merge once.
// ---------------------------------------------------------------------------
__device__ __forceinline__ void fetch_acc(const __half* __restrict__ x,
                                          int c, float v, int sub, float4& acc) {
    uint2 d = __ldg((const uint2*)(x + (size_t)c * DIM) + sub);
    float2 lo = __half22float2(*(const __half2*)&d.x);
    float2 hi = __half22float2(*(const __half2*)&d.y);
    acc.x += v * lo.x;
    acc.y += v * lo.y;
    acc.z += v * hi.x;
    acc.w += v * hi.y;
}

__device__ __forceinline__ void pair_acc(const __half* __restrict__ x,
                                         int4 E, int half, int sub, float4& acc) {
    int   c = half ? E.z : E.x;
    float v = __int_as_float(half ? E.w : E.y);
    fetch_acc(x, c, v, sub, acc);
}

__global__ void __launch_bounds__(256)
spmm_h_kernel(const int*    __restrict__ row_ptr,
              const int2*   __restrict__ edges,
              const __half* __restrict__ x,
              __half*       __restrict__ y) {
    int w    = (int)(((size_t)blockIdx.x * blockDim.x + threadIdx.x) >> 5);
    int lane = threadIdx.x & 31;
    if (w >= N_NODES) return;

    int s = __ldg(row_ptr + w);
    int e = __ldg(row_ptr + w + 1);

    int half = lane >> 4;
    int sub  = lane & 15;
    float4 acc = make_float4(0.f, 0.f, 0.f, 0.f);

    int i = s;
    // head peel to reach even (16B-aligned) edge index
    if ((i & 1) && i < e) {
        int2 E = __ldg(edges + i);
        float v = half ? 0.f : __int_as_float(E.y);
        fetch_acc(x, E.x, v, sub, acc);
        ++i;
    }
    // 8 edges per iteration: 4 int4 edge loads, then 4 independent gathers
    for (; i + 7 < e; i += 8) {
        int4 E0 = __ldg((const int4*)(edges + i));
        int4 E1 = __ldg((const int4*)(edges + i + 2));
        int4 E2 = __ldg((const int4*)(edges + i + 4));
        int4 E3 = __ldg((const int4*)(edges + i + 6));
        pair_acc(x, E0, half, sub, acc);
        pair_acc(x, E1, half, sub, acc);
        pair_acc(x, E2, half, sub, acc);
        pair_acc(x, E3, half, sub, acc);
    }
    // 4-edge step
    for (; i + 3 < e; i += 4) {
        int4 E0 = __ldg((const int4*)(edges + i));
        int4 E1 = __ldg((const int4*)(edges + i + 2));
        pair_acc(x, E0, half, sub, acc);
        pair_acc(x, E1, half, sub, acc);
    }
    // 2-edge step
    for (; i + 1 < e; i += 2) {
        int4 E0 = __ldg((const int4*)(edges + i));
        pair_acc(x, E0, half, sub, acc);
    }
    // tail single edge
    if (i < e) {
        int2 E = __ldg(edges + i);
        float v = half ? 0.f : __int_as_float(E.y);
        fetch_acc(x, E.x, v, sub, acc);
    }

    // merge the two edge-halves (lane l += lane l^16)
    acc.x += __shfl_xor_sync(0xffffffffu, acc.x, 16);
    acc.y += __shfl_xor_sync(0xffffffffu, acc.y, 16);
    acc.z += __shfl_xor_sync(0xffffffffu, acc.z, 16);
    acc.w += __shfl_xor_sync(0xffffffffu, acc.w, 16);

    if (half == 0) {
        __half2 lo = __float22half2_rn(make_float2(acc.x, acc.y));
        __half2 hi = __float22half2_rn(make_float2(acc.z, acc.w));
        uint2 d;
        d.x = *(const unsigned int*)&lo;
        d.y = *(const unsigned int*)&hi;
        ((uint2*)(y + (size_t)w * DIM))[sub] = d;
    }
}

// ---------------------------------------------------------------------------
// final: out = 0.25 * (emb0_fp32 + h1 + h2 + h3)
// ---------------------------------------------------------------------------
__global__ void final_kernel(const float*  __restrict__ ue,
                             const float*  __restrict__ ie,
                             const __half* __restrict__ h1,
                             const __half* __restrict__ h2,
                             const __half* __restrict__ h3,
                             float* __restrict__ out) {
    size_t i = (size_t)blockIdx.x * blockDim.x + threadIdx.x;   // float4 index
    const size_t total = (size_t)N_NODES * DIM / 4;
    if (i >= total) return;
    const size_t uf4 = (size_t)NUM_USERS * DIM / 4;
    float4 v;
    if (i < uf4) v = ((const float4*)ue)[i];
    else         v = ((const float4*)ie)[i - uf4];

    float2 a0 = __half22float2(((const __half2*)h1)[i * 2]);
    float2 a1 = __half22float2(((const __half2*)h1)[i * 2 + 1]);
    float2 b0 = __half22float2(((const __half2*)h2)[i * 2]);
    float2 b1 = __half22float2(((const __half2*)h2)[i * 2 + 1]);
    float2 c0 = __half22float2(((const __half2*)h3)[i * 2]);
    float2 c1 = __half22float2(((const __half2*)h3)[i * 2 + 1]);

    float4 o;
    o.x = 0.25f * (v.x + a0.x + b0.x + c0.x);
    o.y = 0.25f * (v.y + a0.y + b0.y + c0.y);
    o.z = 0.25f * (v.z + a1.x + b1.x + c1.x);
    o.w = 0.25f * (v.w + a1.y + b1.y + c1.y);
    ((float4*)out)[i] = o;
}

// ---------------------------------------------------------------------------
// launch
// ---------------------------------------------------------------------------
extern "C" void kernel_launch(void* const* d_in, const int* in_sizes, int n_in,
                              void* d_out, int out_size) {
    const float* ue   = (const float*)d_in[0];
    const float* ie   = (const float*)d_in[1];
    const float* vals = (const float*)d_in[2];
    const int*   rows = (const int*)d_in[3];
    const int*   cols = (const int*)d_in[4];
    float* out = (float*)d_out;

    __half *h0, *h1, *h2, *h3;
    int2* edges;
    int *cnt, *base, *row_ptr, *blk_sums, *blk_off;
    cudaGetSymbolAddress((void**)&h0, g_h0);
    cudaGetSymbolAddress((void**)&h1, g_h1);
    cudaGetSymbolAddress((void**)&h2, g_h2);
    cudaGetSymbolAddress((void**)&h3, g_h3);
    cudaGetSymbolAddress((void**)&edges, g_edges);
    cudaGetSymbolAddress((void**)&cnt, g_cnt);
    cudaGetSymbolAddress((void**)&base, g_base);
    cudaGetSymbolAddress((void**)&row_ptr, g_row_ptr);
    cudaGetSymbolAddress((void**)&blk_sums, g_blk_sums);
    cudaGetSymbolAddress((void**)&blk_off, g_blk_off);

    const int TPB = 256;
    const size_t nf4 = (size_t)N_NODES * DIM / 4;           // 4.8M float4s
    const int grid_f4   = (int)((nf4 + TPB - 1) / TPB);
    const int grid_node = (N_NODES + TPB - 1) / TPB;
    const int grid_edge = (NNZ + TPB - 1) / TPB;
    const size_t spmm_threads = (size_t)N_NODES * 32;       // warp per row
    const int grid_spmm = (int)((spmm_threads + TPB - 1) / TPB);

    // ---- build row-sorted CSR (amortized over 3 layers) ----
    zero_cnt_kernel<<<grid_node, TPB>>>(cnt);
    hist_kernel<<<grid_edge, TPB>>>(rows, cnt);
    scan1_kernel<<<NB_SCAN, SCAN_TPB>>>(cnt, base, blk_sums);
    scan2_kernel<<<1, 512>>>(blk_sums, blk_off);
    rowptr_kernel<<<grid_node, TPB>>>(base, blk_off, row_ptr);
    scatter_sort_kernel<<<grid_edge, TPB>>>(vals, rows, cols, row_ptr,
                                            cnt, edges);

    // ---- h0 = fp16(concat embeddings) ----
    init_half_kernel<<<grid_f4, TPB>>>(ue, ie, h0);

    // ---- 3 layers of fp16 SpMM ----
    spmm_h_kernel<<<grid_spmm, TPB>>>(row_ptr, edges, h0, h1);
    spmm_h_kernel<<<grid_spmm, TPB>>>(row_ptr, edges, h1, h2);
    spmm_h_kernel<<<grid_spmm, TPB>>>(row_ptr, edges, h2, h3);

    // ---- out = 0.25 * (emb0 + h1 + h2 + h3) ----
    final_kernel<<<grid_f4, TPB>>>(ue, ie, h1, h2, h3, out);
}

// round 16
// speedup vs baseline: 1.2348x; 1.0149x over previous
#include <cuda_runtime.h>
#include <cuda_fp16.h>
#include <cstddef>

#define NUM_USERS 200000
#define NUM_ITEMS 100000
#define N_NODES   (NUM_USERS + NUM_ITEMS)
#define DIM       64
#define NNZ       4000000

#define SCAN_TPB  1024
#define NB_SCAN   ((N_NODES + SCAN_TPB - 1) / SCAN_TPB)   // 293

// Scratch (allocation in kernel_launch is forbidden).
__device__ __half g_h0[(size_t)N_NODES * DIM];
__device__ __half g_h1[(size_t)N_NODES * DIM];
__device__ __half g_h2[(size_t)N_NODES * DIM];
__device__ __align__(16) int2 g_edges[NNZ];   // (col, val-bits), row-sorted
__device__ int    g_cnt[N_NODES];
__device__ int    g_base[N_NODES];
__device__ int    g_row_ptr[N_NODES + 1];
__device__ int    g_blk_sums[NB_SCAN];
__device__ int    g_blk_off[NB_SCAN];

// ---------------------------------------------------------------------------
// init: h0 = fp16(concat(user_emb, item_emb))
// ---------------------------------------------------------------------------
__global__ void init_half_kernel(const float* __restrict__ ue,
                                 const float* __restrict__ ie,
                                 __half* __restrict__ h0) {
    size_t i = (size_t)blockIdx.x * blockDim.x + threadIdx.x;   // float4 index
    const size_t total = (size_t)N_NODES * DIM / 4;
    if (i >= total) return;
    const size_t uf4 = (size_t)NUM_USERS * DIM / 4;
    float4 v;
    if (i < uf4) v = ((const float4*)ue)[i];
    else         v = ((const float4*)ie)[i - uf4];
    __half2 lo = __float22half2_rn(make_float2(v.x, v.y));
    __half2 hi = __float22half2_rn(make_float2(v.z, v.w));
    ((__half2*)h0)[i * 2]     = lo;
    ((__half2*)h0)[i * 2 + 1] = hi;
}

// ---------------------------------------------------------------------------
// CSR build: counting sort of edges by row
// ---------------------------------------------------------------------------
// hist: 4 edges per thread via int4
__global__ void hist_kernel(const int* __restrict__ rows,
                            int* __restrict__ cnt) {
    int t = blockIdx.x * blockDim.x + threadIdx.x;
    int e = t * 4;
    if (e + 3 < NNZ) {
        int4 r = __ldg((const int4*)(rows + e));
        atomicAdd(&cnt[r.x], 1);
        atomicAdd(&cnt[r.y], 1);
        atomicAdd(&cnt[r.z], 1);
        atomicAdd(&cnt[r.w], 1);
    } else {
        for (int k = e; k < NNZ; ++k) atomicAdd(&cnt[rows[k]], 1);
    }
}

// Exclusive scan within each 1024-block (warp-shuffle based); emit totals.
__global__ void scan1_kernel(const int* __restrict__ cnt,
                             int* __restrict__ base,
                             int* __restrict__ blk_sums) {
    __shared__ int wsum[32];
    int i = blockIdx.x * SCAN_TPB + threadIdx.x;
    int lane = threadIdx.x & 31;
    int wid  = threadIdx.x >> 5;
    int v = (i < N_NODES) ? cnt[i] : 0;
    int s = v;
#pragma unroll
    for (int off = 1; off < 32; off <<= 1) {
        int t = __shfl_up_sync(0xffffffffu, s, off);
        if (lane >= off) s += t;
    }
    if (lane == 31) wsum[wid] = s;
    __syncthreads();
    if (wid == 0) {
        int ws = (lane < 32) ? wsum[lane] : 0;
#pragma unroll
        for (int off = 1; off < 32; off <<= 1) {
            int t = __shfl_up_sync(0xffffffffu, ws, off);
            if (lane >= off) ws += t;
        }
        wsum[lane] = ws;
    }
    __syncthreads();
    int wbase = (wid > 0) ? wsum[wid - 1] : 0;
    if (i < N_NODES) base[i] = wbase + s - v;        // exclusive
    if (threadIdx.x == SCAN_TPB - 1) blk_sums[blockIdx.x] = wbase + s;
}

__global__ void scan2_kernel(const int* __restrict__ blk_sums,
                             int* __restrict__ blk_off) {
    __shared__ int s[512];
    int i = threadIdx.x;
    int v = (i < NB_SCAN) ? blk_sums[i] : 0;
    s[i] = v;
    __syncthreads();
    for (int off = 1; off < 512; off <<= 1) {
        int t = (i >= off) ? s[i - off] : 0;
        __syncthreads();
        s[i] += t;
        __syncthreads();
    }
    if (i < NB_SCAN) blk_off[i] = s[i] - v;          // exclusive
}

__global__ void rowptr_kernel(const int* __restrict__ base,
                              const int* __restrict__ blk_off,
                              int* __restrict__ row_ptr) {
    int i = blockIdx.x * blockDim.x + threadIdx.x;
    if (i < N_NODES) row_ptr[i] = base[i] + blk_off[i >> 10];
    if (i == 0)      row_ptr[N_NODES] = NNZ;
}

// Permute edges into row-sorted order. cnt (degrees) is consumed as a
// countdown cursor: position = row_ptr[r] + (--cnt[r]).
__global__ void scatter_sort_kernel(const float* __restrict__ vals,
                                    const int*   __restrict__ rows,
                                    const int*   __restrict__ cols,
                                    const int*   __restrict__ row_ptr,
                                    int*         __restrict__ cnt,
                                    int2*        __restrict__ edges) {
    int e = blockIdx.x * blockDim.x + threadIdx.x;
    if (e >= NNZ) return;
    int r = rows[e];
    int p = row_ptr[r] + atomicAdd(&cnt[r], -1) - 1;
    edges[p] = make_int2(cols[e], __float_as_int(vals[e]));
}

// ---------------------------------------------------------------------------
// spmm core: one warp per row; 16 lanes per edge -> TWO edges per gather LDG.
// 8 edges/iteration: 4 int4 edge loads, then 4 independent paired gathers.
// ---------------------------------------------------------------------------
__device__ __forceinline__ void fetch_acc(const __half* __restrict__ x,
                                          int c, float v, int sub, float4& acc) {
    uint2 d = __ldg((const uint2*)(x + (size_t)c * DIM) + sub);
    float2 lo = __half22float2(*(const __half2*)&d.x);
    float2 hi = __half22float2(*(const __half2*)&d.y);
    acc.x += v * lo.x;
    acc.y += v * lo.y;
    acc.z += v * hi.x;
    acc.w += v * hi.y;
}

__device__ __forceinline__ void pair_acc(const __half* __restrict__ x,
                                         int4 E, int half, int sub, float4& acc) {
    int   c = half ? E.z : E.x;
    float v = __int_as_float(half ? E.w : E.y);
    fetch_acc(x, c, v, sub, acc);
}

__device__ __forceinline__ float4 row_accumulate(const int2* __restrict__ edges,
                                                 const __half* __restrict__ x,
                                                 int s, int e, int half, int sub) {
    float4 acc = make_float4(0.f, 0.f, 0.f, 0.f);
    int i = s;
    if ((i & 1) && i < e) {           // head peel to even index
        int2 E = __ldg(edges + i);
        float v = half ? 0.f : __int_as_float(E.y);
        fetch_acc(x, E.x, v, sub, acc);
        ++i;
    }
    for (; i + 7 < e; i += 8) {
        int4 E0 = __ldg((const int4*)(edges + i));
        int4 E1 = __ldg((const int4*)(edges + i + 2));
        int4 E2 = __ldg((const int4*)(edges + i + 4));
        int4 E3 = __ldg((const int4*)(edges + i + 6));
        pair_acc(x, E0, half, sub, acc);
        pair_acc(x, E1, half, sub, acc);
        pair_acc(x, E2, half, sub, acc);
        pair_acc(x, E3, half, sub, acc);
    }
    for (; i + 3 < e; i += 4) {
        int4 E0 = __ldg((const int4*)(edges + i));
        int4 E1 = __ldg((const int4*)(edges + i + 2));
        pair_acc(x, E0, half, sub, acc);
        pair_acc(x, E1, half, sub, acc);
    }
    for (; i + 1 < e; i += 2) {
        int4 E0 = __ldg((const int4*)(edges + i));
        pair_acc(x, E0, half, sub, acc);
    }
    if (i < e) {
        int2 E = __ldg(edges + i);
        float v = half ? 0.f : __int_as_float(E.y);
        fetch_acc(x, E.x, v, sub, acc);
    }
    // merge the two edge-halves (lane l += lane l^16)
    acc.x += __shfl_xor_sync(0xffffffffu, acc.x, 16);
    acc.y += __shfl_xor_sync(0xffffffffu, acc.y, 16);
    acc.z += __shfl_xor_sync(0xffffffffu, acc.z, 16);
    acc.w += __shfl_xor_sync(0xffffffffu, acc.w, 16);
    return acc;
}

// layer 1 & 2: y = A * x (fp16 out)
__global__ void __launch_bounds__(256)
spmm_h_kernel(const int*    __restrict__ row_ptr,
              const int2*   __restrict__ edges,
              const __half* __restrict__ x,
              __half*       __restrict__ y) {
    int w    = (int)(((size_t)blockIdx.x * blockDim.x + threadIdx.x) >> 5);
    int lane = threadIdx.x & 31;
    if (w >= N_NODES) return;
    int s = __ldg(row_ptr + w);
    int e = __ldg(row_ptr + w + 1);
    int half = lane >> 4;
    int sub  = lane & 15;

    float4 acc = row_accumulate(edges, x, s, e, half, sub);

    if (half == 0) {
        __half2 lo = __float22half2_rn(make_float2(acc.x, acc.y));
        __half2 hi = __float22half2_rn(make_float2(acc.z, acc.w));
        uint2 d;
        d.x = *(const unsigned int*)&lo;
        d.y = *(const unsigned int*)&hi;
        ((uint2*)(y + (size_t)w * DIM))[sub] = d;
    }
}

// layer 3 fused with final: out = 0.25*(emb0_fp32 + h1 + h2 + A*h2)
__global__ void __launch_bounds__(256)
spmm_final_kernel(const int*    __restrict__ row_ptr,
                  const int2*   __restrict__ edges,
                  const __half* __restrict__ x,     // = h2
                  const __half* __restrict__ h1,
                  const float*  __restrict__ ue,
                  const float*  __restrict__ ie,
                  float*        __restrict__ out) {
    int w    = (int)(((size_t)blockIdx.x * blockDim.x + threadIdx.x) >> 5);
    int lane = threadIdx.x & 31;
    if (w >= N_NODES) return;
    int s = __ldg(row_ptr + w);
    int e = __ldg(row_ptr + w + 1);
    int half = lane >> 4;
    int sub  = lane & 15;

    float4 acc = row_accumulate(edges, x, s, e, half, sub);

    if (half == 0) {
        // emb0 (fp32): float4 chunk `sub` of row w
        const float* src = (w < NUM_USERS) ? (ue + (size_t)w * DIM)
                                           : (ie + (size_t)(w - NUM_USERS) * DIM);
        float4 e0 = __ldg((const float4*)src + sub);
        // h1, h2 rows (fp16): uint2 chunk `sub`
        uint2 d1 = __ldg((const uint2*)(h1 + (size_t)w * DIM) + sub);
        uint2 d2 = __ldg((const uint2*)(x  + (size_t)w * DIM) + sub);
        float2 a0 = __half22float2(*(const __half2*)&d1.x);
        float2 a1 = __half22float2(*(const __half2*)&d1.y);
        float2 b0 = __half22float2(*(const __half2*)&d2.x);
        float2 b1 = __half22float2(*(const __half2*)&d2.y);
        float4 o;
        o.x = 0.25f * (e0.x + a0.x + b0.x + acc.x);
        o.y = 0.25f * (e0.y + a0.y + b0.y + acc.y);
        o.z = 0.25f * (e0.z + a1.x + b1.x + acc.z);
        o.w = 0.25f * (e0.w + a1.y + b1.y + acc.w);
        ((float4*)(out + (size_t)w * DIM))[sub] = o;
    }
}

// ---------------------------------------------------------------------------
// launch
// ---------------------------------------------------------------------------
extern "C" void kernel_launch(void* const* d_in, const int* in_sizes, int n_in,
                              void* d_out, int out_size) {
    const float* ue   = (const float*)d_in[0];
    const float* ie   = (const float*)d_in[1];
    const float* vals = (const float*)d_in[2];
    const int*   rows = (const int*)d_in[3];
    const int*   cols = (const int*)d_in[4];
    float* out = (float*)d_out;

    __half *h0, *h1, *h2;
    int2* edges;
    int *cnt, *base, *row_ptr, *blk_sums, *blk_off;
    cudaGetSymbolAddress((void**)&h0, g_h0);
    cudaGetSymbolAddress((void**)&h1, g_h1);
    cudaGetSymbolAddress((void**)&h2, g_h2);
    cudaGetSymbolAddress((void**)&edges, g_edges);
    cudaGetSymbolAddress((void**)&cnt, g_cnt);
    cudaGetSymbolAddress((void**)&base, g_base);
    cudaGetSymbolAddress((void**)&row_ptr, g_row_ptr);
    cudaGetSymbolAddress((void**)&blk_sums, g_blk_sums);
    cudaGetSymbolAddress((void**)&blk_off, g_blk_off);

    const int TPB = 256;
    const size_t nf4 = (size_t)N_NODES * DIM / 4;           // 4.8M float4s
    const int grid_f4   = (int)((nf4 + TPB - 1) / TPB);
    const int grid_node = (N_NODES + TPB - 1) / TPB;
    const int grid_edge = (NNZ + TPB - 1) / TPB;
    const int grid_hist = (NNZ / 4 + TPB - 1) / TPB;
    const size_t spmm_threads = (size_t)N_NODES * 32;       // warp per row
    const int grid_spmm = (int)((spmm_threads + TPB - 1) / TPB);

    // ---- build row-sorted CSR (amortized over 3 layers) ----
    cudaMemsetAsync(cnt, 0, N_NODES * sizeof(int));
    hist_kernel<<<grid_hist, TPB>>>(rows, cnt);
    scan1_kernel<<<NB_SCAN, SCAN_TPB>>>(cnt, base, blk_sums);
    scan2_kernel<<<1, 512>>>(blk_sums, blk_off);
    rowptr_kernel<<<grid_node, TPB>>>(base, blk_off, row_ptr);
    scatter_sort_kernel<<<grid_edge, TPB>>>(vals, rows, cols, row_ptr,
                                            cnt, edges);

    // ---- h0 = fp16(concat embeddings) ----
    init_half_kernel<<<grid_f4, TPB>>>(ue, ie, h0);

    // ---- layers 1-2 (fp16), layer 3 fused with final reduction ----
    spmm_h_kernel<<<grid_spmm, TPB>>>(row_ptr, edges, h0, h1);
    spmm_h_kernel<<<grid_spmm, TPB>>>(row_ptr, edges, h1, h2);
    spmm_final_kernel<<<grid_spmm, TPB>>>(row_ptr, edges, h2, h1, ue, ie, out);
}